// round 16
// baseline (speedup 1.0000x reference)
#include <cuda_runtime.h>
#include <cuda_bf16.h>

// Problem constants
#define T   2048
#define D   2048
#define NH  16
#define DH  128
#define DRH 64
#define DC  512
#define QKD 192   // DH + DRH

#define SCALE 0.07216878364870323f   // 1/sqrt(192)

// -------- scratch (device globals; no allocation allowed) --------
__device__ float g_ckv[(size_t)T * DC];
__device__ float g_cq [(size_t)T * DC];
__device__ float g_q  [(size_t)NH * T * QKD];
__device__ float g_k  [(size_t)NH * T * QKD];
__device__ float g_v  [(size_t)NH * T * QKD];   // padded to QKD stride (cols 0..127 used)
__device__ float g_kr [(size_t)T * DRH];
__device__ float g_logits[(size_t)NH * T * T];
__device__ float g_attn[(size_t)T * NH * DH];
__device__ float g_wot [(size_t)D * NH * DH];
__device__ float g_sm [(size_t)NH * T];          // row max (scaled)
__device__ float g_si [(size_t)NH * T];          // 1 / row sum

typedef unsigned long long ull;

__device__ __forceinline__ void ffma2(ull& d, ull a, ull b) {
    asm("fma.rn.f32x2 %0, %1, %2, %0;" : "+l"(d) : "l"(a), "l"(b));
}
__device__ __forceinline__ ull dup2(float x) {
    ull r;
    asm("mov.b64 %0, {%1, %1};" : "=l"(r) : "f"(x));
    return r;
}
union F2u { ull u; float2 f; };

__device__ __forceinline__ unsigned f2tf(float x) {
    unsigned r;
    asm("cvt.rna.tf32.f32 %0, %1;" : "=r"(r) : "f"(x));
    return r;
}

__device__ __forceinline__ void mma8(float* c, const unsigned* a, const unsigned* b) {
    asm("mma.sync.aligned.m16n8k8.row.col.f32.tf32.tf32.f32 "
        "{%0,%1,%2,%3}, {%4,%5,%6,%7}, {%8,%9}, {%0,%1,%2,%3};"
        : "+f"(c[0]), "+f"(c[1]), "+f"(c[2]), "+f"(c[3])
        : "r"(a[0]), "r"(a[1]), "r"(a[2]), "r"(a[3]), "r"(b[0]), "r"(b[1]));
}

// ============================================================
// TF32 mma.sync GEMM core: 128x128 tile, BK=8, 256 threads (8 warps),
// warp tile 64x32, 2 CTAs/SM.
// ============================================================

__device__ __forceinline__ int a_word8(int m, int k) {
    int t = (m & 7) * 4 + (k & 3);
    int r = ((k >> 2) << 1) | ((m >> 3) & 1);
    int w = (t * 4) ^ (((t >> 2) & 7) << 2);
    return (m >> 4) * 128 + w + r;
}
__device__ __forceinline__ int b_word8(int n, int k) {
    int t = (n & 7) * 4 + (k & 3);
    int r = k >> 2;
    int w = (t * 2) ^ (((t >> 2) & 7) << 1);
    return (n >> 3) * 64 + w + r;
}

template<bool TN, bool RED>
__device__ __forceinline__ void tf32_body(
    const float* __restrict__ A, const float* __restrict__ B, float* __restrict__ C,
    int kbeg, int kend, int lda, int ldb, int ldc, int bm, int bn)
{
    __shared__ __align__(16) unsigned As[2][1024];
    __shared__ __align__(16) unsigned Bs[2][1024];
    if (TN) { A += (long long)kbeg * lda; B += (long long)kbeg * ldb; }
    else    { A += kbeg; B += kbeg; }
    const int K = kend - kbeg;

    const int tid = threadIdx.x;
    const int lane = tid & 31;
    const int wid = tid >> 5;
    const int wm = (wid & 1) * 4;
    const int wn = (wid >> 1) * 4;

    float acc[4][4][4];
#pragma unroll
    for (int x = 0; x < 4; ++x)
#pragma unroll
        for (int y = 0; y < 4; ++y)
#pragma unroll
            for (int z = 0; z < 4; ++z) acc[x][y][z] = 0.0f;

    int r0, c0;
    if (!TN) { r0 = tid >> 1; c0 = (tid & 1) * 4; }
    else     { r0 = tid >> 5; c0 = (tid & 31) * 4; }

    const int ntl = K / 8;
    float4 a0, b0;

    if (!TN) {
        a0 = *(const float4*)(A + (long long)(bm + r0) * lda + c0);
        b0 = *(const float4*)(B + (long long)(bn + r0) * ldb + c0);
    } else {
        a0 = *(const float4*)(A + (long long)r0 * lda + bm + c0);
        b0 = *(const float4*)(B + (long long)r0 * ldb + bn + c0);
    }

    int buf = 0;
    {
        const float* av = (const float*)&a0;
        const float* bv = (const float*)&b0;
        if (!TN) {
#pragma unroll
            for (int j = 0; j < 4; ++j) {
                As[0][a_word8(r0, c0 + j)] = f2tf(av[j]);
                Bs[0][b_word8(r0, c0 + j)] = f2tf(bv[j]);
            }
        } else {
#pragma unroll
            for (int j = 0; j < 4; ++j) {
                As[0][a_word8(c0 + j, r0)] = f2tf(av[j]);
                Bs[0][b_word8(c0 + j, r0)] = f2tf(bv[j]);
            }
        }
    }
    __syncthreads();

    for (int it = 0; it < ntl; ++it) {
        if (it + 1 < ntl) {
            const int k0 = (it + 1) * 8;
            if (!TN) {
                a0 = *(const float4*)(A + (long long)(bm + r0) * lda + k0 + c0);
                b0 = *(const float4*)(B + (long long)(bn + r0) * ldb + k0 + c0);
            } else {
                a0 = *(const float4*)(A + (long long)(k0 + r0) * lda + bm + c0);
                b0 = *(const float4*)(B + (long long)(k0 + r0) * ldb + bn + c0);
            }
        }
        const unsigned* Asb = As[buf];
        const unsigned* Bsb = Bs[buf];
        {
            unsigned af[4][4];
            unsigned bfm[4][2];
            const int aoff = (lane * 4) ^ (((lane >> 2) & 7) << 2);
            const int boff = (lane * 2) ^ (((lane >> 2) & 7) << 1);
#pragma unroll
            for (int mt = 0; mt < 4; ++mt) {
                uint4 w = *(const uint4*)&Asb[(wm + mt) * 128 + aoff];
                af[mt][0] = w.x; af[mt][1] = w.y; af[mt][2] = w.z; af[mt][3] = w.w;
            }
#pragma unroll
            for (int nt = 0; nt < 4; ++nt) {
                uint2 w = *(const uint2*)&Bsb[(wn + nt) * 64 + boff];
                bfm[nt][0] = w.x;
                bfm[nt][1] = w.y;
            }
#pragma unroll
            for (int mt = 0; mt < 4; ++mt)
#pragma unroll
                for (int nt = 0; nt < 4; ++nt)
                    mma8(acc[mt][nt], af[mt], bfm[nt]);
        }
        if (it + 1 < ntl) {
            buf ^= 1;
            const float* av = (const float*)&a0;
            const float* bv = (const float*)&b0;
            if (!TN) {
#pragma unroll
                for (int j = 0; j < 4; ++j) {
                    As[buf][a_word8(r0, c0 + j)] = f2tf(av[j]);
                    Bs[buf][b_word8(r0, c0 + j)] = f2tf(bv[j]);
                }
            } else {
#pragma unroll
                for (int j = 0; j < 4; ++j) {
                    As[buf][a_word8(c0 + j, r0)] = f2tf(av[j]);
                    Bs[buf][b_word8(c0 + j, r0)] = f2tf(bv[j]);
                }
            }
            __syncthreads();
        }
    }

    const int gid = lane >> 2;
    const int tig = lane & 3;
#pragma unroll
    for (int mt = 0; mt < 4; ++mt) {
        const long long row = bm + (wm + mt) * 16 + gid;
#pragma unroll
        for (int nt = 0; nt < 4; ++nt) {
            const int col = bn + (wn + nt) * 8 + tig * 2;
            if (RED) {
                atomicAdd(C + row * ldc + col,           acc[mt][nt][0]);
                atomicAdd(C + row * ldc + col + 1,       acc[mt][nt][1]);
                atomicAdd(C + (row + 8) * ldc + col,     acc[mt][nt][2]);
                atomicAdd(C + (row + 8) * ldc + col + 1, acc[mt][nt][3]);
            } else {
                *(float2*)(C + row * ldc + col) = make_float2(acc[mt][nt][0], acc[mt][nt][1]);
                *(float2*)(C + (row + 8) * ldc + col) = make_float2(acc[mt][nt][2], acc[mt][nt][3]);
            }
        }
    }
}

// Generic strided-batch wrapper (CMODE: 0 plain, 1 causal tile-skip)
template<bool TN, int CMODE>
__global__ __launch_bounds__(256, 2) void gemm_tf32(
    const float* __restrict__ A, const float* __restrict__ B, float* __restrict__ C,
    int K, int lda, int ldb, int ldc,
    long long sA, long long sB, long long sC)
{
    const int bm = blockIdx.y * 128;
    const int bn = blockIdx.x * 128;
    if (CMODE == 1 && bn > bm) return;
    tf32_body<TN, false>(A + (long long)blockIdx.z * sA,
                         B + (long long)blockIdx.z * sB,
                         C + (long long)blockIdx.z * sC,
                         0, K, lda, ldb, ldc, bm, bn);
}

// Down-projections, split-K x2: z = sel*2 + khalf; RED epilogue into zeroed C.
__global__ __launch_bounds__(256, 2) void gemm_down_split(
    const float* __restrict__ h, const float* __restrict__ w_dkv,
    const float* __restrict__ w_dq, float* __restrict__ ckv, float* __restrict__ cq)
{
    const int sel = blockIdx.z >> 1;
    const int kh = blockIdx.z & 1;
    const float* B = sel ? w_dq : w_dkv;
    float* C = sel ? cq : ckv;
    tf32_body<false, true>(h, B, C, kh * (D / 2), (kh + 1) * (D / 2),
                           D, D, DC, blockIdx.y * 128, blockIdx.x * 128);
}

// Up-projections merged: z = sel*16 + head. All dims uniform (K=DC, ldc=QKD).
__global__ __launch_bounds__(256, 2) void gemm_up(
    const float* __restrict__ ckv, const float* __restrict__ cq,
    const float* __restrict__ w_uk, const float* __restrict__ w_uv,
    const float* __restrict__ w_uq,
    float* __restrict__ k, float* __restrict__ v, float* __restrict__ q)
{
    const int sel = blockIdx.z >> 4;
    const int head = blockIdx.z & 15;
    const float* A = (sel == 2) ? cq : ckv;
    const float* B = (sel == 0 ? w_uk : (sel == 1 ? w_uv : w_uq)) + head * DC;
    float* C = (sel == 0 ? k : (sel == 1 ? v : q)) + (long long)head * T * QKD;
    tf32_body<false, false>(A, B, C, 0, DC, DC, NH * DC, QKD, blockIdx.y * 128, 0);
}

// ============================================================
// Fused attention output: out[n,l,e] = sum_{t>=l} S[n,t,l] v[n,t,e]
// with S computed on the fly from raw logits + row stats (m, 1/s).
// Split-K x2 over the causal range [bm, T). RED epilogue into zeroed attn.
// TN staging: each warp stages one k-row t -> m_t, is_t are warp-uniform.
// ============================================================
__global__ __launch_bounds__(256, 2) void gemm_attn_fused(
    const float* __restrict__ logits, const float* __restrict__ v, float* __restrict__ attn,
    const float* __restrict__ smg, const float* __restrict__ sig)
{
    __shared__ __align__(16) unsigned As[2][1024];
    __shared__ __align__(16) unsigned Bs[2][1024];
    const int bm = blockIdx.y * 128;             // l-tile base
    const int half = (T - bm) >> 1;              // multiple of 64
    const int kbeg = bm + blockIdx.x * half;
    const long long zh = blockIdx.z;
    const float* A = logits + zh * T * T + (long long)kbeg * T;       // rows = t
    const float* B = v + zh * (long long)T * QKD + (long long)kbeg * QKD;
    float* C = attn + zh * DH;
    const float* smh = smg + zh * T;
    const float* sih = sig + zh * T;
    const int K = half;

    const int tid = threadIdx.x;
    const int lane = tid & 31;
    const int wid = tid >> 5;
    const int wm = (wid & 1) * 4;
    const int wn = (wid >> 1) * 4;

    float acc[4][4][4];
#pragma unroll
    for (int x = 0; x < 4; ++x)
#pragma unroll
        for (int y = 0; y < 4; ++y)
#pragma unroll
            for (int z = 0; z < 4; ++z) acc[x][y][z] = 0.0f;

    const int r0 = tid >> 5;            // k-row within tile (warp id)
    const int c0 = (tid & 31) * 4;      // column (l for A, e for B)
    const int ntl = K / 8;
    float4 a0, b0;

    a0 = *(const float4*)(A + (long long)r0 * T + bm + c0);
    b0 = *(const float4*)(B + (long long)r0 * QKD + c0);

    int buf = 0;
    {
        const int t_idx = kbeg + r0;
        const float mval = __ldg(smh + t_idx);
        const float ival = __ldg(sih + t_idx);
        const float* av = (const float*)&a0;
        const float* bv = (const float*)&b0;
#pragma unroll
        for (int j = 0; j < 4; ++j) {
            const int l = bm + c0 + j;
            float p = (l <= t_idx) ? __expf(av[j] * SCALE - mval) * ival : 0.0f;
            As[0][a_word8(c0 + j, r0)] = f2tf(p);
            Bs[0][b_word8(c0 + j, r0)] = f2tf(bv[j]);
        }
    }
    __syncthreads();

    for (int it = 0; it < ntl; ++it) {
        if (it + 1 < ntl) {
            const int k0 = (it + 1) * 8;
            a0 = *(const float4*)(A + (long long)(k0 + r0) * T + bm + c0);
            b0 = *(const float4*)(B + (long long)(k0 + r0) * QKD + c0);
        }
        const unsigned* Asb = As[buf];
        const unsigned* Bsb = Bs[buf];
        {
            unsigned af[4][4];
            unsigned bfm[4][2];
            const int aoff = (lane * 4) ^ (((lane >> 2) & 7) << 2);
            const int boff = (lane * 2) ^ (((lane >> 2) & 7) << 1);
#pragma unroll
            for (int mt = 0; mt < 4; ++mt) {
                uint4 w = *(const uint4*)&Asb[(wm + mt) * 128 + aoff];
                af[mt][0] = w.x; af[mt][1] = w.y; af[mt][2] = w.z; af[mt][3] = w.w;
            }
#pragma unroll
            for (int nt = 0; nt < 4; ++nt) {
                uint2 w = *(const uint2*)&Bsb[(wn + nt) * 64 + boff];
                bfm[nt][0] = w.x;
                bfm[nt][1] = w.y;
            }
#pragma unroll
            for (int mt = 0; mt < 4; ++mt)
#pragma unroll
                for (int nt = 0; nt < 4; ++nt)
                    mma8(acc[mt][nt], af[mt], bfm[nt]);
        }
        if (it + 1 < ntl) {
            buf ^= 1;
            const int t_idx = kbeg + (it + 1) * 8 + r0;
            const float mval = __ldg(smh + t_idx);
            const float ival = __ldg(sih + t_idx);
            const float* av = (const float*)&a0;
            const float* bv = (const float*)&b0;
#pragma unroll
            for (int j = 0; j < 4; ++j) {
                const int l = bm + c0 + j;
                float p = (l <= t_idx) ? __expf(av[j] * SCALE - mval) * ival : 0.0f;
                As[buf][a_word8(c0 + j, r0)] = f2tf(p);
                Bs[buf][b_word8(c0 + j, r0)] = f2tf(bv[j]);
            }
            __syncthreads();
        }
    }

    const int gid = lane >> 2;
    const int tig = lane & 3;
#pragma unroll
    for (int mt = 0; mt < 4; ++mt) {
        const long long row = bm + (wm + mt) * 16 + gid;
#pragma unroll
        for (int nt = 0; nt < 4; ++nt) {
            const int col = (wn + nt) * 8 + tig * 2;
            atomicAdd(C + row * (NH * DH) + col,           acc[mt][nt][0]);
            atomicAdd(C + row * (NH * DH) + col + 1,       acc[mt][nt][1]);
            atomicAdd(C + (row + 8) * (NH * DH) + col,     acc[mt][nt][2]);
            atomicAdd(C + (row + 8) * (NH * DH) + col + 1, acc[mt][nt][3]);
        }
    }
}

// Zero-fill (float4)
__global__ void zero_f4(float4* p, int n4)
{
    int i = blockIdx.x * blockDim.x + threadIdx.x;
    if (i < n4) p[i] = make_float4(0.f, 0.f, 0.f, 0.f);
}

// ============================================================
// 64x64 fp32 GEMM (N=64 cases: k_r, q_r) — FFMA2 mainloop
// ============================================================
#define SM_ 64
#define SK_ 16
__global__ __launch_bounds__(256) void gemm_nt64(
    const float* __restrict__ A, const float* __restrict__ B, float* __restrict__ C,
    int K, int lda, int ldb, int ldc,
    long long sA, long long sB, long long sC)
{
    __shared__ float As[SK_][SM_];
    __shared__ float Bs[SK_][SM_];
    A += (long long)blockIdx.z * sA;
    B += (long long)blockIdx.z * sB;
    C += (long long)blockIdx.z * sC;
    const int bm = blockIdx.y * SM_;
    const int bn = blockIdx.x * SM_;
    const int tid = threadIdx.x;
    const int tx = tid & 15;
    const int ty = tid >> 4;
    const int lrow = tid >> 2;
    const int lcol = (tid & 3) * 4;

    ull acc2[2][4] = {};

    for (int k0 = 0; k0 < K; k0 += SK_) {
        float4 a = *(const float4*)(A + (long long)(bm + lrow) * lda + k0 + lcol);
        float4 b = *(const float4*)(B + (long long)(bn + lrow) * ldb + k0 + lcol);
        __syncthreads();
        As[lcol + 0][lrow] = a.x; As[lcol + 1][lrow] = a.y;
        As[lcol + 2][lrow] = a.z; As[lcol + 3][lrow] = a.w;
        Bs[lcol + 0][lrow] = b.x; Bs[lcol + 1][lrow] = b.y;
        Bs[lcol + 2][lrow] = b.z; Bs[lcol + 3][lrow] = b.w;
        __syncthreads();
#pragma unroll
        for (int kk = 0; kk < SK_; ++kk) {
            float4 av = *(const float4*)(&As[kk][ty * 4]);
            float4 bv = *(const float4*)(&Bs[kk][tx * 4]);
            ull ap[2];
            ap[0] = ((const ull*)&av)[0];
            ap[1] = ((const ull*)&av)[1];
            ull bb[4];
            bb[0] = dup2(bv.x); bb[1] = dup2(bv.y);
            bb[2] = dup2(bv.z); bb[3] = dup2(bv.w);
#pragma unroll
            for (int p = 0; p < 2; ++p)
#pragma unroll
                for (int j = 0; j < 4; ++j)
                    ffma2(acc2[p][j], ap[p], bb[j]);
        }
    }

#pragma unroll
    for (int p = 0; p < 2; ++p) {
#pragma unroll
        for (int half = 0; half < 2; ++half) {
            const int crow = bm + ty * 4 + p * 2 + half;
            F2u v0, v1, v2, v3;
            v0.u = acc2[p][0]; v1.u = acc2[p][1];
            v2.u = acc2[p][2]; v3.u = acc2[p][3];
            float4 o = half ? make_float4(v0.f.y, v1.f.y, v2.f.y, v3.f.y)
                            : make_float4(v0.f.x, v1.f.x, v2.f.x, v3.f.x);
            *(float4*)(C + (long long)crow * ldc + bn + tx * 4) = o;
        }
    }
}

// ============================================================
// Elementwise kernels
// ============================================================
__global__ void rope_q_kernel(float* __restrict__ q, const float* __restrict__ freqs)
{
    int idx = blockIdx.x * blockDim.x + threadIdx.x;   // NH*T*32
    int i = idx & 31;
    int t = (idx >> 5) & (T - 1);
    int n = idx >> 16;
    float ang = freqs[t * (DRH / 2) + i];
    float c, s;
    __sincosf(ang, &s, &c);
    float* base = q + ((size_t)(n * T + t)) * QKD + DH;
    float re = base[i], im = base[i + 32];
    base[i]      = re * c - im * s;
    base[i + 32] = re * s + im * c;
}

__global__ void rope_k_bcast_kernel(const float* __restrict__ kr, float* __restrict__ kbuf,
                                    const float* __restrict__ freqs)
{
    int idx = blockIdx.x * blockDim.x + threadIdx.x;   // T*32
    int i = idx & 31;
    int t = idx >> 5;
    float ang = freqs[t * (DRH / 2) + i];
    float c, s;
    __sincosf(ang, &s, &c);
    float re = kr[t * DRH + i], im = kr[t * DRH + 32 + i];
    const float inv_nh = 1.0f / (float)NH;
    float rr = (re * c - im * s) * inv_nh;
    float ri = (re * s + im * c) * inv_nh;
#pragma unroll
    for (int n = 0; n < NH; ++n) {
        float* b = kbuf + ((size_t)(n * T + t)) * QKD + DH;
        b[i]      = rr;
        b[i + 32] = ri;
    }
}

__global__ void wo_transpose_kernel(const float* __restrict__ wo, float* __restrict__ wt)
{
    int idx = blockIdx.x * blockDim.x + threadIdx.x;   // D * NH * DH
    int j = idx & (NH * DH - 1);
    int d = idx >> 11;
    int n = j >> 7;
    int e = j & (DH - 1);
    wt[idx] = wo[(size_t)d * (DH * NH) + e * NH + n];
}

// Row softmax stats: m_t = max over l<=t of z*scale; is_t = 1/sum(exp(v - m)).
// Does NOT write S — attn computes it on the fly.
__global__ __launch_bounds__(256) void softmax_stats(
    const float* __restrict__ logits, float* __restrict__ smg, float* __restrict__ sig,
    float scale)
{
    const int t = blockIdx.x;
    const int n = blockIdx.y;
    const float* __restrict__ row = logits + ((size_t)n * T + t) * T;
    const int tid = threadIdx.x;
    const int wbase = tid & ~31;

    float v[8];
    float mx = -1e30f;
#pragma unroll
    for (int j = 0; j < 8; ++j) {
        const int l = tid + j * 256;
        if (wbase + j * 256 > t) {
            v[j] = -1e30f;
        } else {
            float x = row[l];
            v[j] = (l <= t) ? x * scale : -1e30f;
        }
        mx = fmaxf(mx, v[j]);
    }
    __shared__ float redm[8], reds[8];
#pragma unroll
    for (int o = 16; o; o >>= 1) mx = fmaxf(mx, __shfl_xor_sync(0xffffffffu, mx, o));
    if ((tid & 31) == 0) redm[tid >> 5] = mx;
    __syncthreads();
    mx = redm[0];
#pragma unroll
    for (int w = 1; w < 8; ++w) mx = fmaxf(mx, redm[w]);

    float sum = 0.0f;
#pragma unroll
    for (int j = 0; j < 8; ++j) {
        if (v[j] > -1e29f) sum += __expf(v[j] - mx);
    }
#pragma unroll
    for (int o = 16; o; o >>= 1) sum += __shfl_xor_sync(0xffffffffu, sum, o);
    if ((tid & 31) == 0) reds[tid >> 5] = sum;
    __syncthreads();
    if (tid == 0) {
        sum = reds[0];
#pragma unroll
        for (int w = 1; w < 8; ++w) sum += reds[w];
        smg[(size_t)n * T + t] = mx;
        sig[(size_t)n * T + t] = 1.0f / sum;
    }
}

// ============================================================
// Launch
// ============================================================
extern "C" void kernel_launch(void* const* d_in, const int* in_sizes, int n_in,
                              void* d_out, int out_size)
{
    const float* h     = (const float*)d_in[0];
    const float* freqs = (const float*)d_in[1];
    const float* w_dkv = (const float*)d_in[3];
    const float* w_uk  = (const float*)d_in[4];
    const float* w_uv  = (const float*)d_in[5];
    const float* w_dq  = (const float*)d_in[6];
    const float* w_uq  = (const float*)d_in[7];
    const float* w_qr  = (const float*)d_in[8];
    const float* w_kr  = (const float*)d_in[9];
    const float* w_o   = (const float*)d_in[10];
    float* out = (float*)d_out;
    (void)in_sizes; (void)n_in; (void)out_size;

    float *ckv, *cq, *q, *k, *v, *kr, *logits, *attn, *wot, *sm, *si;
    cudaGetSymbolAddress((void**)&ckv,    g_ckv);
    cudaGetSymbolAddress((void**)&cq,     g_cq);
    cudaGetSymbolAddress((void**)&q,      g_q);
    cudaGetSymbolAddress((void**)&k,      g_k);
    cudaGetSymbolAddress((void**)&v,      g_v);
    cudaGetSymbolAddress((void**)&kr,     g_kr);
    cudaGetSymbolAddress((void**)&logits, g_logits);
    cudaGetSymbolAddress((void**)&attn,   g_attn);
    cudaGetSymbolAddress((void**)&wot,    g_wot);
    cudaGetSymbolAddress((void**)&sm,     g_sm);
    cudaGetSymbolAddress((void**)&si,     g_si);

    const dim3 blk(256);
    const long long sQ = (long long)T * QKD;

    // Zero split-K accumulation targets
    zero_f4<<<(T * DC / 4 + 255) / 256, 256>>>((float4*)ckv, T * DC / 4);
    zero_f4<<<(T * DC / 4 + 255) / 256, 256>>>((float4*)cq,  T * DC / 4);
    zero_f4<<<(T * NH * DH / 4 + 255) / 256, 256>>>((float4*)attn, T * NH * DH / 4);

    // Latents: c_kv + c_q, split-K x2 (256 blocks, K=1024 each)
    gemm_down_split<<<dim3(DC / 128, T / 128, 4), blk>>>(h, w_dkv, w_dq, ckv, cq);
    // k_r (pre-rope): N=64, fp32
    gemm_nt64<<<dim3(1, T / SM_, 1), 256>>>(h, w_kr, kr, D, D, D, DRH, 0, 0, 0);

    // Per-head up-projections, merged (768 blocks, all dims uniform)
    gemm_up<<<dim3(1, T / 128, 3 * NH), blk>>>(ckv, cq, w_uk, w_uv, w_uq, k, v, q);
    // q_r: N=64, fp32
    gemm_nt64<<<dim3(1, T / SM_, NH), 256>>>(cq, w_qr, q + DH, DC, DC, NH * DC, QKD, 0, DC, sQ);

    // Rope
    rope_q_kernel<<<(NH * T * 32) / 256, 256>>>(q, freqs);
    rope_k_bcast_kernel<<<(T * 32) / 256, 256>>>(kr, k, freqs);

    // logits[n,t,l] = q . k  — skip fully-masked upper tiles
    gemm_tf32<false, 1><<<dim3(T / 128, T / 128, NH), blk>>>(q, k, logits, QKD, QKD, QKD, T, sQ, sQ, (long long)T * T);

    // softmax row stats only (no S write)
    softmax_stats<<<dim3(T, NH), 256>>>(logits, sm, si, SCALE);

    // fused attn: S computed on the fly; split-K x2 over causal range
    gemm_attn_fused<<<dim3(2, T / 128, NH), blk>>>(logits, v, attn, sm, si);

    // w_o permute then final projection
    wo_transpose_kernel<<<(D * NH * DH) / 256, 256>>>(w_o, wot);
    gemm_tf32<false, 0><<<dim3(D / 128, T / 128, 1), blk>>>(attn, wot, out, NH * DH, NH * DH, NH * DH, D, 0, 0, 0);
}